// round 2
// baseline (speedup 1.0000x reference)
#include <cuda_runtime.h>
#include <stdint.h>

// TopK masking: out = x * mask(top-64 per row), x: [B, 4096] fp32.
//
// One CTA per row, 256 threads, 16 elements/thread held in registers as
// order-preserving uint32 keys. Exact k-th largest via 4-pass radix-256
// select with warp-aggregated smem histogram + parallel suffix scan.
// Single GMEM read + single GMEM write per element (512 MB total traffic).

#define THREADS 256
#define FDIM 4096
#define PER_THREAD (FDIM / THREADS)   // 16
#define KSEL 64

__device__ __forceinline__ unsigned int f2key(float f) {
    unsigned int b = __float_as_uint(f);
    // monotone map: larger float -> larger uint
    return (b & 0x80000000u) ? ~b : (b | 0x80000000u);
}

__device__ __forceinline__ float key2f(unsigned int k) {
    return (k & 0x80000000u) ? __uint_as_float(k & 0x7FFFFFFFu)
                             : __uint_as_float(~k);
}

__global__ void __launch_bounds__(THREADS, 8)
topk_mask_kernel(const float* __restrict__ x, float* __restrict__ out) {
    const int row = blockIdx.x;
    const int t   = threadIdx.x;

    const float4* xrow = reinterpret_cast<const float4*>(x + (size_t)row * FDIM);
    float4*       orow = reinterpret_cast<float4*>(out + (size_t)row * FDIM);

    __shared__ unsigned int hist[256];
    __shared__ unsigned int suf[256];
    __shared__ unsigned int s_prefix;
    __shared__ unsigned int s_kth;
    __shared__ unsigned int s_taken;

    // ---- load row, convert to sortable keys in registers ----
    unsigned int keys[PER_THREAD];
    #pragma unroll
    for (int v = 0; v < PER_THREAD / 4; v++) {
        float4 f4 = xrow[t + v * THREADS];
        keys[v * 4 + 0] = f2key(f4.x);
        keys[v * 4 + 1] = f2key(f4.y);
        keys[v * 4 + 2] = f2key(f4.z);
        keys[v * 4 + 3] = f2key(f4.w);
    }

    // ---- 4-pass radix-256 select for the KSEL-th largest key ----
    unsigned int prefix = 0;          // resolved high bits of threshold key
    unsigned int kth    = KSEL;       // rank still needed within current prefix

    #pragma unroll 1
    for (int pass = 0; pass < 4; pass++) {
        const int shift = 24 - 8 * pass;
        const unsigned int pmask = (pass == 0) ? 0u : (0xFFFFFFFFu << (shift + 8));

        hist[t] = 0;                  // THREADS == 256
        __syncthreads();

        // warp-aggregated histogram (values cluster in few exponent bins;
        // plain atomics would serialize hundreds deep on one address)
        #pragma unroll
        for (int i = 0; i < PER_THREAD; i++) {
            const unsigned int kk  = keys[i];
            const bool active      = ((kk & pmask) == prefix);
            const unsigned int act = __ballot_sync(0xFFFFFFFFu, active);
            if (active) {
                const unsigned int bin   = (kk >> shift) & 0xFFu;
                const unsigned int peers = __match_any_sync(act, bin);
                if ((t & 31) == (__ffs(peers) - 1))
                    atomicAdd(&hist[bin], __popc(peers));
            }
        }
        __syncthreads();

        // inclusive suffix scan over 256 bins (Hillis-Steele, 8 steps)
        const unsigned int h = hist[t];
        suf[t] = h;
        __syncthreads();
        #pragma unroll
        for (int d = 1; d < 256; d <<= 1) {
            const unsigned int v = (t + d < 256) ? suf[t + d] : 0u;
            __syncthreads();
            suf[t] += v;
            __syncthreads();
        }

        // exactly one bin satisfies: (count > bin) < kth <= (count >= bin)
        const unsigned int incl = suf[t];
        const unsigned int excl = incl - h;
        if (excl < kth && incl >= kth) {
            s_prefix = prefix | ((unsigned int)t << shift);
            s_kth    = kth - excl;
        }
        __syncthreads();
        prefix = s_prefix;
        kth    = s_kth;
    }
    // prefix == exact KSEL-th largest key; kth == budget among ties

    if (t == 0) s_taken = 0;
    __syncthreads();
    const unsigned int thresh = prefix;
    const unsigned int budget = kth;

    // ---- write masked output (coalesced float4 stores) ----
    #pragma unroll
    for (int v = 0; v < PER_THREAD / 4; v++) {
        float4 o;
        float* op = &o.x;
        #pragma unroll
        for (int j = 0; j < 4; j++) {
            const unsigned int kk = keys[v * 4 + j];
            float val = 0.0f;
            if (kk > thresh) {
                val = key2f(kk);
            } else if (kk == thresh) {
                if (atomicAdd(&s_taken, 1u) < budget) val = key2f(kk);
            }
            op[j] = val;
        }
        orow[t + v * THREADS] = o;
    }
}

extern "C" void kernel_launch(void* const* d_in, const int* in_sizes, int n_in,
                              void* d_out, int out_size) {
    const float* x = (const float*)d_in[0];
    float* out     = (float*)d_out;
    const int B    = in_sizes[0] / FDIM;   // 16384
    topk_mask_kernel<<<B, THREADS>>>(x, out);
}

// round 3
// speedup vs baseline: 1.5647x; 1.5647x over previous
#include <cuda_runtime.h>
#include <stdint.h>

// TopK masking: out = x * mask(top-64 per row), x: [16384, 4096] fp32.
//
// One CTA per row, 256 threads, 16 floats/thread in registers.
// Fast path: pre-filter at TGUESS=1.9 (top-64 threshold of N(0,1)~2.14, so
// candidates n~118+-11; n>=64 is a 5-sigma certainty), compact candidates to
// smem, exact selection by rank-counting (gt-only + packed atomicMax).
// Exact radix-256 fallback if the candidate count is ever out of range.
// One GMEM read + one GMEM write per element; tie budget keeps exactly k.

#define THREADS 256
#define FDIM 4096
#define PER_THREAD 16
#define KSEL 64u
#define TGUESS 1.9f
#define CAP 512u

__device__ __forceinline__ unsigned int f2key(float f) {
    unsigned int b = __float_as_uint(f);
    return (b & 0x80000000u) ? ~b : (b | 0x80000000u);
}
__device__ __forceinline__ float key2f(unsigned int k) {
    return (k & 0x80000000u) ? __uint_as_float(k & 0x7FFFFFFFu)
                             : __uint_as_float(~k);
}

__global__ void __launch_bounds__(THREADS, 8)
topk_mask_kernel(const float* __restrict__ x, float* __restrict__ out) {
    const int row  = blockIdx.x;
    const int t    = threadIdx.x;
    const int lane = t & 31;

    __shared__ float        cand[CAP];
    __shared__ unsigned int s_n;
    __shared__ unsigned int s_pack;   // (gt << 16) | candidate_index
    __shared__ unsigned int s_taken;
    __shared__ unsigned int hist[256];        // fallback only
    __shared__ unsigned int s_prefix, s_kth;  // fallback only
    __shared__ float        s_thresh;         // fallback only
    __shared__ unsigned int s_budget;         // fallback only

    if (t == 0) { s_n = 0; s_pack = 0; s_taken = 0; }

    const float4* xrow = reinterpret_cast<const float4*>(x + (size_t)row * FDIM);
    float4*       orow = reinterpret_cast<float4*>(out + (size_t)row * FDIM);

    // ---- load row into registers ----
    float vals[PER_THREAD];
    #pragma unroll
    for (int v = 0; v < 4; v++) {
        float4 f4 = xrow[t + v * THREADS];
        vals[v * 4 + 0] = f4.x;
        vals[v * 4 + 1] = f4.y;
        vals[v * 4 + 2] = f4.z;
        vals[v * 4 + 3] = f4.w;
    }
    __syncthreads();  // s_n/s_pack/s_taken init visible

    // ---- compact candidates (> TGUESS) into smem, warp-aggregated ----
    #pragma unroll
    for (int i = 0; i < PER_THREAD; i++) {
        const float v = vals[i];
        const bool  p = (v > TGUESS);
        const unsigned bal = __ballot_sync(0xFFFFFFFFu, p);
        if (bal) {
            const int leader = __ffs(bal) - 1;
            unsigned base = 0;
            if (lane == leader) base = atomicAdd(&s_n, (unsigned)__popc(bal));
            base = __shfl_sync(0xFFFFFFFFu, base, leader);
            if (p) {
                const unsigned pos = base + __popc(bal & ((1u << lane) - 1u));
                if (pos < CAP) cand[pos] = v;
            }
        }
    }
    __syncthreads();
    const unsigned n = s_n;

    float    thresh;
    unsigned budget;

    if (n >= KSEL && n <= CAP) {
        // ---- fast path: exact rank-counting over n candidates ----
        const unsigned npad = (n + 3u) & ~3u;          // pad for float4 loads
        if ((unsigned)t < npad - n) cand[n + t] = -1e30f;
        __syncthreads();

        const float4* c4 = reinterpret_cast<const float4*>(cand);
        for (unsigned ci = t; ci < n; ci += THREADS) {
            const float c = cand[ci];
            unsigned gt = 0;
            const unsigned n4 = npad >> 2;
            for (unsigned j = 0; j < n4; j++) {
                const float4 o = c4[j];
                gt += (o.x > c) + (o.y > c) + (o.z > c) + (o.w > c);
            }
            // threshold = candidate with the LARGEST gt that is still < KSEL
            if (gt < KSEL) atomicMax(&s_pack, (gt << 16) | ci);
        }
        __syncthreads();
        const unsigned pk = s_pack;
        thresh = cand[pk & 0xFFFFu];
        budget = KSEL - (pk >> 16);
    } else {
        // ---- fallback: exact 4-pass radix-256 select (practically never runs) ----
        unsigned keys[PER_THREAD];
        #pragma unroll
        for (int i = 0; i < PER_THREAD; i++) keys[i] = f2key(vals[i]);

        unsigned prefix = 0, kth = KSEL;
        for (int pass = 0; pass < 4; pass++) {
            const int shift = 24 - 8 * pass;
            const unsigned pmask = pass ? (0xFFFFFFFFu << (shift + 8)) : 0u;
            hist[t] = 0;
            __syncthreads();
            #pragma unroll
            for (int i = 0; i < PER_THREAD; i++) {
                if ((keys[i] & pmask) == prefix)
                    atomicAdd(&hist[(keys[i] >> shift) & 0xFFu], 1u);
            }
            __syncthreads();
            if (t == 0) {
                unsigned acc = 0;
                int b = 256;
                do { b--; acc += hist[b]; } while (acc < kth && b > 0);
                s_prefix = prefix | ((unsigned)b << shift);
                s_kth    = kth - (acc - hist[b]);
            }
            __syncthreads();
            prefix = s_prefix;
            kth    = s_kth;
        }
        if (t == 0) { s_thresh = key2f(prefix); s_budget = kth; }
        __syncthreads();
        thresh = s_thresh;
        budget = s_budget;
    }

    // ---- masked write (coalesced float4 stores, exact tie budget) ----
    #pragma unroll
    for (int v = 0; v < 4; v++) {
        float4 o;
        float* op = &o.x;
        #pragma unroll
        for (int j = 0; j < 4; j++) {
            const float val = vals[v * 4 + j];
            float w = 0.0f;
            if (val > thresh) {
                w = val;
            } else if (val == thresh) {
                if (atomicAdd(&s_taken, 1u) < budget) w = val;
            }
            op[j] = w;
        }
        orow[t + v * THREADS] = o;
    }
}

extern "C" void kernel_launch(void* const* d_in, const int* in_sizes, int n_in,
                              void* d_out, int out_size) {
    const float* x = (const float*)d_in[0];
    float* out     = (float*)d_out;
    const int B    = in_sizes[0] / FDIM;   // 16384
    topk_mask_kernel<<<B, THREADS>>>(x, out);
}